// round 1
// baseline (speedup 1.0000x reference)
#include <cuda_runtime.h>
#include <cstdint>

#define N_ENTITIES 100000
#define N_USERS    50000
#define N_FACTORS  4
#define N_RELATIONS 32
#define N_META     8
#define CHANNEL    64
#define N_EDGES    1600000
#define NNZ_CNT    1000000

// Scratch (no device allocation allowed; __device__ globals are the sanctioned path)
__device__ float g_cnt[N_ENTITIES];
__device__ float g_disen[N_FACTORS * CHANNEL];

__device__ __forceinline__ void red_add_v2(float* p, float x, float y) {
    asm volatile("red.global.add.v2.f32 [%0], {%1,%2};"
                 :: "l"(p), "f"(x), "f"(y) : "memory");
}

// ---------------------------------------------------------------------------
// 0) zero output accumulators + counts
// ---------------------------------------------------------------------------
__global__ void zero_kernel(float* __restrict__ out) {
    int i = blockIdx.x * blockDim.x + threadIdx.x;
    const int total = (N_ENTITIES + N_USERS) * CHANNEL;
    if (i < total) out[i] = 0.0f;
    if (i < N_ENTITIES) g_cnt[i] = 0.0f;
}

// ---------------------------------------------------------------------------
// 1) disen_weight = softmax(disen_weight_att, axis=-1) @ weight   (4 x 64)
//    one block of 64 threads; thread c computes column c for all 4 factors
// ---------------------------------------------------------------------------
__global__ void disen_kernel(const float* __restrict__ att,     // (4, 8)
                             const float* __restrict__ weight)  // (8, 64)
{
    int c = threadIdx.x;
    if (c >= CHANNEL) return;
    #pragma unroll
    for (int f = 0; f < N_FACTORS; f++) {
        float a[N_META];
        float m = -1e30f;
        #pragma unroll
        for (int j = 0; j < N_META; j++) { a[j] = att[f * N_META + j]; m = fmaxf(m, a[j]); }
        float s = 0.0f;
        #pragma unroll
        for (int j = 0; j < N_META; j++) { a[j] = __expf(a[j] - m); s += a[j]; }
        float inv = 1.0f / s;
        float acc = 0.0f;
        #pragma unroll
        for (int j = 0; j < N_META; j++) acc += a[j] * inv * weight[j * CHANNEL + c];
        g_disen[f * CHANNEL + c] = acc;
    }
}

// ---------------------------------------------------------------------------
// 2) KG edge aggregation: one warp per edge, float2 per lane
// ---------------------------------------------------------------------------
__global__ void edge_kernel(const float* __restrict__ ent,      // (N_ENTITIES, 64)
                            const int*   __restrict__ head,
                            const int*   __restrict__ tail,
                            const int*   __restrict__ etype,
                            const float* __restrict__ relw,     // (31, 64)
                            float* __restrict__ out_ent)        // (N_ENTITIES, 64)
{
    __shared__ float s_rel[(N_RELATIONS - 1) * CHANNEL];
    for (int i = threadIdx.x; i < (N_RELATIONS - 1) * CHANNEL; i += blockDim.x)
        s_rel[i] = relw[i];
    __syncthreads();

    int e    = blockIdx.x * (blockDim.x >> 5) + (threadIdx.x >> 5);
    int lane = threadIdx.x & 31;
    if (e >= N_EDGES) return;

    int h = head[e];
    int t = tail[e];
    int r = etype[e] - 1;

    float2 rel = *(const float2*)&s_rel[r * CHANNEL + lane * 2];
    float2 eh  = *(const float2*)&ent[(size_t)h * CHANNEL + lane * 2];

    float partial = eh.x * rel.x + eh.y * rel.y;
    #pragma unroll
    for (int o = 16; o > 0; o >>= 1) partial += __shfl_xor_sync(0xFFFFFFFFu, partial, o);
    float att = 1.0f / (1.0f + __expf(-partial));

    float2 et = *(const float2*)&ent[(size_t)t * CHANNEL + lane * 2];
    red_add_v2(&out_ent[(size_t)h * CHANNEL + lane * 2],
               att * et.x * rel.x, att * et.y * rel.y);
    if (lane == 0)
        asm volatile("red.global.add.f32 [%0], %1;" :: "l"(&g_cnt[h]), "f"(1.0f) : "memory");
}

// ---------------------------------------------------------------------------
// 3) sparse mm: one warp per nnz
// ---------------------------------------------------------------------------
__global__ void spmm_kernel(const float* __restrict__ ent,
                            const int*   __restrict__ mrow,
                            const int*   __restrict__ mcol,
                            const float* __restrict__ mval,
                            float* __restrict__ out_user)       // (N_USERS, 64)
{
    int i    = blockIdx.x * (blockDim.x >> 5) + (threadIdx.x >> 5);
    int lane = threadIdx.x & 31;
    if (i >= NNZ_CNT) return;

    int   r = mrow[i];
    int   c = mcol[i];
    float v = mval[i];
    float2 e = *(const float2*)&ent[(size_t)c * CHANNEL + lane * 2];
    red_add_v2(&out_user[(size_t)r * CHANNEL + lane * 2], v * e.x, v * e.y);
}

// ---------------------------------------------------------------------------
// 4) entity finalize: scatter_mean divide
// ---------------------------------------------------------------------------
__global__ void entity_final_kernel(float* __restrict__ out_ent) {
    int i = blockIdx.x * blockDim.x + threadIdx.x;
    if (i >= N_ENTITIES * CHANNEL) return;
    float c = g_cnt[i >> 6];  // i / CHANNEL
    out_ent[i] = out_ent[i] / fmaxf(c, 1.0f);
}

// ---------------------------------------------------------------------------
// 5) user finalize: score softmax + disen blend.  one warp per user
// ---------------------------------------------------------------------------
__global__ void user_final_kernel(const float* __restrict__ user_emb,  // (U, 64)
                                  const float* __restrict__ latent,    // (4, 64)
                                  float* __restrict__ out_user)
{
    __shared__ float s_lat[N_FACTORS * CHANNEL];
    __shared__ float s_dis[N_FACTORS * CHANNEL];
    for (int i = threadIdx.x; i < N_FACTORS * CHANNEL; i += blockDim.x) {
        s_lat[i] = latent[i];
        s_dis[i] = g_disen[i];
    }
    __syncthreads();

    int u    = blockIdx.x * (blockDim.x >> 5) + (threadIdx.x >> 5);
    int lane = threadIdx.x & 31;
    if (u >= N_USERS) return;

    float2 ue = *(const float2*)&user_emb[(size_t)u * CHANNEL + lane * 2];

    float s[N_FACTORS];
    #pragma unroll
    for (int f = 0; f < N_FACTORS; f++) {
        float p = ue.x * s_lat[f * CHANNEL + lane * 2]
                + ue.y * s_lat[f * CHANNEL + lane * 2 + 1];
        #pragma unroll
        for (int o = 16; o > 0; o >>= 1) p += __shfl_xor_sync(0xFFFFFFFFu, p, o);
        s[f] = p;
    }
    float m = fmaxf(fmaxf(s[0], s[1]), fmaxf(s[2], s[3]));
    float sum = 0.0f;
    #pragma unroll
    for (int f = 0; f < N_FACTORS; f++) { s[f] = __expf(s[f] - m); sum += s[f]; }
    float inv = 1.0f / sum;

    float cx = 0.0f, cy = 0.0f;
    #pragma unroll
    for (int f = 0; f < N_FACTORS; f++) {
        float sc = s[f] * inv;
        cx += sc * s_dis[f * CHANNEL + lane * 2];
        cy += sc * s_dis[f * CHANNEL + lane * 2 + 1];
    }

    float2* p = (float2*)&out_user[(size_t)u * CHANNEL + lane * 2];
    float2 a = *p;
    a.x = a.x * (1.0f + cx);
    a.y = a.y * (1.0f + cy);
    *p = a;
}

// ---------------------------------------------------------------------------
extern "C" void kernel_launch(void* const* d_in, const int* in_sizes, int n_in,
                              void* d_out, int out_size)
{
    const float* entity_emb = (const float*)d_in[0];
    const float* user_emb   = (const float*)d_in[1];
    const float* latent_emb = (const float*)d_in[2];
    const int*   head       = (const int*)d_in[3];
    const int*   tail       = (const int*)d_in[4];
    const int*   edge_type  = (const int*)d_in[5];
    const int*   mat_row    = (const int*)d_in[6];
    const int*   mat_col    = (const int*)d_in[7];
    const float* mat_val    = (const float*)d_in[8];
    const float* rel_w      = (const float*)d_in[9];
    const float* weight     = (const float*)d_in[10];
    const float* disen_att  = (const float*)d_in[11];

    float* out      = (float*)d_out;
    float* out_ent  = out;                               // (N_ENTITIES, 64)
    float* out_user = out + (size_t)N_ENTITIES * CHANNEL; // (N_USERS, 64)

    const int total = (N_ENTITIES + N_USERS) * CHANNEL;
    zero_kernel<<<(total + 255) / 256, 256>>>(out);
    disen_kernel<<<1, 64>>>(disen_att, weight);

    // 8 warps per block
    edge_kernel<<<(N_EDGES + 7) / 8, 256>>>(entity_emb, head, tail, edge_type,
                                            rel_w, out_ent);
    spmm_kernel<<<(NNZ_CNT + 7) / 8, 256>>>(entity_emb, mat_row, mat_col, mat_val,
                                            out_user);

    entity_final_kernel<<<(N_ENTITIES * CHANNEL + 255) / 256, 256>>>(out_ent);
    user_final_kernel<<<(N_USERS + 7) / 8, 256>>>(user_emb, latent_emb, out_user);
}

// round 2
// speedup vs baseline: 1.9403x; 1.9403x over previous
#include <cuda_runtime.h>
#include <cstdint>

#define N_ENTITIES 100000
#define N_USERS    50000
#define N_FACTORS  4
#define N_RELATIONS 32
#define N_META     8
#define CHANNEL    64
#define N_EDGES    1600000
#define NNZ_CNT    1000000

// Scratch (device-global; no allocation allowed)
__device__ float g_cnt[N_ENTITIES];
__device__ float g_disen[N_FACTORS * CHANNEL];

__device__ __forceinline__ void red_add_v4(float* p, float x, float y, float z, float w) {
    asm volatile("red.global.add.v4.f32 [%0], {%1,%2,%3,%4};"
                 :: "l"(p), "f"(x), "f"(y), "f"(z), "f"(w) : "memory");
}

// ---------------------------------------------------------------------------
// 0) zero output accumulators + counts (float4 stores)
// ---------------------------------------------------------------------------
__global__ void zero_kernel(float4* __restrict__ out) {
    int i = blockIdx.x * blockDim.x + threadIdx.x;
    const int total4 = (N_ENTITIES + N_USERS) * CHANNEL / 4;
    if (i < total4) out[i] = make_float4(0.f, 0.f, 0.f, 0.f);
    if (i < N_ENTITIES) g_cnt[i] = 0.0f;
}

// ---------------------------------------------------------------------------
// 1) disen_weight = softmax(disen_weight_att, axis=-1) @ weight   (4 x 64)
// ---------------------------------------------------------------------------
__global__ void disen_kernel(const float* __restrict__ att,     // (4, 8)
                             const float* __restrict__ weight)  // (8, 64)
{
    int c = threadIdx.x;
    if (c >= CHANNEL) return;
    #pragma unroll
    for (int f = 0; f < N_FACTORS; f++) {
        float a[N_META];
        float m = -1e30f;
        #pragma unroll
        for (int j = 0; j < N_META; j++) { a[j] = att[f * N_META + j]; m = fmaxf(m, a[j]); }
        float s = 0.0f;
        #pragma unroll
        for (int j = 0; j < N_META; j++) { a[j] = __expf(a[j] - m); s += a[j]; }
        float inv = 1.0f / s;
        float acc = 0.0f;
        #pragma unroll
        for (int j = 0; j < N_META; j++) acc += a[j] * inv * weight[j * CHANNEL + c];
        g_disen[f * CHANNEL + c] = acc;
    }
}

// ---------------------------------------------------------------------------
// 2) KG edge aggregation: one HALF-WARP per edge, float4 per lane
//    16 lanes x 4 floats = one 64-float row; red.v4 halves atomic op count
// ---------------------------------------------------------------------------
__global__ void edge_kernel(const float* __restrict__ ent,      // (N_ENTITIES, 64)
                            const int*   __restrict__ head,
                            const int*   __restrict__ tail,
                            const int*   __restrict__ etype,
                            const float* __restrict__ relw,     // (31, 64)
                            float* __restrict__ out_ent)        // (N_ENTITIES, 64)
{
    __shared__ float s_rel[(N_RELATIONS - 1) * CHANNEL];
    for (int i = threadIdx.x; i < (N_RELATIONS - 1) * CHANNEL; i += blockDim.x)
        s_rel[i] = relw[i];
    __syncthreads();

    // 256 threads = 16 half-warps = 16 edges per block
    int e  = blockIdx.x * 16 + (threadIdx.x >> 4);
    int li = threadIdx.x & 15;
    if (e >= N_EDGES) return;

    int h = head[e];
    int t = tail[e];
    int r = etype[e] - 1;

    float4 rel = *(const float4*)&s_rel[r * CHANNEL + li * 4];
    float4 eh  = *(const float4*)&ent[(size_t)h * CHANNEL + li * 4];
    float4 et  = *(const float4*)&ent[(size_t)t * CHANNEL + li * 4];

    float partial = eh.x * rel.x + eh.y * rel.y + eh.z * rel.z + eh.w * rel.w;
    #pragma unroll
    for (int o = 8; o > 0; o >>= 1) partial += __shfl_xor_sync(0xFFFFFFFFu, partial, o);
    float att = 1.0f / (1.0f + __expf(-partial));

    red_add_v4(&out_ent[(size_t)h * CHANNEL + li * 4],
               att * et.x * rel.x, att * et.y * rel.y,
               att * et.z * rel.z, att * et.w * rel.w);
    if (li == 0)
        asm volatile("red.global.add.f32 [%0], %1;" :: "l"(&g_cnt[h]), "f"(1.0f) : "memory");
}

// ---------------------------------------------------------------------------
// 3) sparse mm: one HALF-WARP per nnz, float4 per lane
// ---------------------------------------------------------------------------
__global__ void spmm_kernel(const float* __restrict__ ent,
                            const int*   __restrict__ mrow,
                            const int*   __restrict__ mcol,
                            const float* __restrict__ mval,
                            float* __restrict__ out_user)       // (N_USERS, 64)
{
    int i  = blockIdx.x * 16 + (threadIdx.x >> 4);
    int li = threadIdx.x & 15;
    if (i >= NNZ_CNT) return;

    int   r = mrow[i];
    int   c = mcol[i];
    float v = mval[i];
    float4 e = *(const float4*)&ent[(size_t)c * CHANNEL + li * 4];
    red_add_v4(&out_user[(size_t)r * CHANNEL + li * 4],
               v * e.x, v * e.y, v * e.z, v * e.w);
}

// ---------------------------------------------------------------------------
// 4) entity finalize: scatter_mean divide (float4)
// ---------------------------------------------------------------------------
__global__ void entity_final_kernel(float4* __restrict__ out_ent) {
    int i = blockIdx.x * blockDim.x + threadIdx.x;          // float4 index
    if (i >= N_ENTITIES * (CHANNEL / 4)) return;
    float c = fmaxf(g_cnt[i >> 4], 1.0f);                   // 16 float4 per row
    float inv = 1.0f / c;
    float4 v = out_ent[i];
    v.x *= inv; v.y *= inv; v.z *= inv; v.w *= inv;
    out_ent[i] = v;
}

// ---------------------------------------------------------------------------
// 5) user finalize: score softmax + disen blend.  one warp per user
// ---------------------------------------------------------------------------
__global__ void user_final_kernel(const float* __restrict__ user_emb,  // (U, 64)
                                  const float* __restrict__ latent,    // (4, 64)
                                  float* __restrict__ out_user)
{
    __shared__ float s_lat[N_FACTORS * CHANNEL];
    __shared__ float s_dis[N_FACTORS * CHANNEL];
    for (int i = threadIdx.x; i < N_FACTORS * CHANNEL; i += blockDim.x) {
        s_lat[i] = latent[i];
        s_dis[i] = g_disen[i];
    }
    __syncthreads();

    int u    = blockIdx.x * (blockDim.x >> 5) + (threadIdx.x >> 5);
    int lane = threadIdx.x & 31;
    if (u >= N_USERS) return;

    float2 ue = *(const float2*)&user_emb[(size_t)u * CHANNEL + lane * 2];

    float s[N_FACTORS];
    #pragma unroll
    for (int f = 0; f < N_FACTORS; f++) {
        float p = ue.x * s_lat[f * CHANNEL + lane * 2]
                + ue.y * s_lat[f * CHANNEL + lane * 2 + 1];
        #pragma unroll
        for (int o = 16; o > 0; o >>= 1) p += __shfl_xor_sync(0xFFFFFFFFu, p, o);
        s[f] = p;
    }
    float m = fmaxf(fmaxf(s[0], s[1]), fmaxf(s[2], s[3]));
    float sum = 0.0f;
    #pragma unroll
    for (int f = 0; f < N_FACTORS; f++) { s[f] = __expf(s[f] - m); sum += s[f]; }
    float inv = 1.0f / sum;

    float cx = 0.0f, cy = 0.0f;
    #pragma unroll
    for (int f = 0; f < N_FACTORS; f++) {
        float sc = s[f] * inv;
        cx += sc * s_dis[f * CHANNEL + lane * 2];
        cy += sc * s_dis[f * CHANNEL + lane * 2 + 1];
    }

    float2* p = (float2*)&out_user[(size_t)u * CHANNEL + lane * 2];
    float2 a = *p;
    a.x = a.x * (1.0f + cx);
    a.y = a.y * (1.0f + cy);
    *p = a;
}

// ---------------------------------------------------------------------------
extern "C" void kernel_launch(void* const* d_in, const int* in_sizes, int n_in,
                              void* d_out, int out_size)
{
    const float* entity_emb = (const float*)d_in[0];
    const float* user_emb   = (const float*)d_in[1];
    const float* latent_emb = (const float*)d_in[2];
    const int*   head       = (const int*)d_in[3];
    const int*   tail       = (const int*)d_in[4];
    const int*   edge_type  = (const int*)d_in[5];
    const int*   mat_row    = (const int*)d_in[6];
    const int*   mat_col    = (const int*)d_in[7];
    const float* mat_val    = (const float*)d_in[8];
    const float* rel_w      = (const float*)d_in[9];
    const float* weight     = (const float*)d_in[10];
    const float* disen_att  = (const float*)d_in[11];

    float* out      = (float*)d_out;
    float* out_ent  = out;                                // (N_ENTITIES, 64)
    float* out_user = out + (size_t)N_ENTITIES * CHANNEL; // (N_USERS, 64)

    const int total4 = (N_ENTITIES + N_USERS) * CHANNEL / 4;
    zero_kernel<<<(total4 + 255) / 256, 256>>>((float4*)out);
    disen_kernel<<<1, 64>>>(disen_att, weight);

    edge_kernel<<<(N_EDGES + 15) / 16, 256>>>(entity_emb, head, tail, edge_type,
                                              rel_w, out_ent);
    spmm_kernel<<<(NNZ_CNT + 15) / 16, 256>>>(entity_emb, mat_row, mat_col, mat_val,
                                              out_user);

    entity_final_kernel<<<(N_ENTITIES * (CHANNEL / 4) + 255) / 256, 256>>>((float4*)out_ent);
    user_final_kernel<<<(N_USERS + 7) / 8, 256>>>(user_emb, latent_emb, out_user);
}